// round 2
// baseline (speedup 1.0000x reference)
#include <cuda_runtime.h>
#include <cuda_bf16.h>
#include <cstdint>

// ---------------------------------------------------------------------------
// 2-layer GRU (H=32, INPUT=4, B=4096, S=512) + FC(32->32) + FC(32->1)
//
// Mapping: one warp per batch row, one lane per hidden unit (H == 32).
// Weights are register-resident per lane; h broadcast via __shfl_sync.
// Pass 1 writes h1[B,S,32] to a __device__ scratch; pass 2 consumes it,
// runs layer 2, and applies the two FC layers at the end.
// ---------------------------------------------------------------------------

#define B_ROWS 4096
#define SEQ    512
#define HID    32

// 4096*512*32 floats = 268 MB scratch (allowed: static __device__ array)
__device__ float g_h1[(size_t)B_ROWS * SEQ * HID];

__device__ __forceinline__ float sigmoidf_fast(float a) {
    float e = __expf(-a);
    return __fdividef(1.0f, 1.0f + e);
}
__device__ __forceinline__ float tanhf_fast(float a) {
    // tanh(x) = 1 - 2/(exp(2x)+1); robust at +-inf
    float e = __expf(2.0f * a);
    return 1.0f - __fdividef(2.0f, e + 1.0f);
}

// ---------------------------------------------------------------------------
// Pass 1: GRU layer 1.  x:[B,S,4] -> h1:[B,S,32]
// ---------------------------------------------------------------------------
__global__ __launch_bounds__(128)
void gru_layer1_kernel(const float* __restrict__ x,
                       const float* __restrict__ Wih,   // [96,4]
                       const float* __restrict__ Whh,   // [96,32]
                       const float* __restrict__ bih,   // [96]
                       const float* __restrict__ bhh)   // [96]
{
    const int warp = (blockIdx.x * blockDim.x + threadIdx.x) >> 5;
    const int lane = threadIdx.x & 31;
    if (warp >= B_ROWS) return;

    // Per-lane weight rows (lane i -> gate rows i, 32+i, 64+i)
    float wir[4], wiz[4], win[4];
#pragma unroll
    for (int k = 0; k < 4; k++) {
        wir[k] = Wih[(lane)      * 4 + k];
        wiz[k] = Wih[(32 + lane) * 4 + k];
        win[k] = Wih[(64 + lane) * 4 + k];
    }
    float whr[HID], whz[HID], whn[HID];
#pragma unroll
    for (int j = 0; j < HID; j++) {
        whr[j] = Whh[(lane)      * HID + j];
        whz[j] = Whh[(32 + lane) * HID + j];
        whn[j] = Whh[(64 + lane) * HID + j];
    }
    // Combined biases: r and z gates can merge b_ih + b_hh; n gate must not.
    const float br = bih[lane]      + bhh[lane];
    const float bz = bih[32 + lane] + bhh[32 + lane];
    const float bin = bih[64 + lane];
    const float bhn = bhh[64 + lane];

    const float4* xp = reinterpret_cast<const float4*>(x + (size_t)warp * SEQ * 4);
    float* op = g_h1 + (size_t)warp * SEQ * HID + lane;

    float h = 0.0f;
#pragma unroll 1
    for (int s = 0; s < SEQ; s++) {
        const float4 xv = __ldg(xp + s);

        float ar = br;   // r-gate accumulator: x-part + h-part + both biases
        float az = bz;
        float xn = bin;  // n-gate x-part
        float hn = bhn;  // n-gate h-part (scaled by r later)

        ar = fmaf(wir[0], xv.x, ar); ar = fmaf(wir[1], xv.y, ar);
        ar = fmaf(wir[2], xv.z, ar); ar = fmaf(wir[3], xv.w, ar);
        az = fmaf(wiz[0], xv.x, az); az = fmaf(wiz[1], xv.y, az);
        az = fmaf(wiz[2], xv.z, az); az = fmaf(wiz[3], xv.w, az);
        xn = fmaf(win[0], xv.x, xn); xn = fmaf(win[1], xv.y, xn);
        xn = fmaf(win[2], xv.z, xn); xn = fmaf(win[3], xv.w, xn);

#pragma unroll
        for (int j = 0; j < HID; j++) {
            const float hj = __shfl_sync(0xffffffffu, h, j);
            ar = fmaf(whr[j], hj, ar);
            az = fmaf(whz[j], hj, az);
            hn = fmaf(whn[j], hj, hn);
        }

        const float r = sigmoidf_fast(ar);
        const float z = sigmoidf_fast(az);
        const float n = tanhf_fast(fmaf(r, hn, xn));
        h = fmaf(z, h - n, n);

        op[(size_t)s * HID] = h;
    }
}

// ---------------------------------------------------------------------------
// Pass 2: GRU layer 2 + FC(32->32) + FC(32->1).  h1:[B,S,32] -> out:[B,1]
// ---------------------------------------------------------------------------
__global__ __launch_bounds__(128)
void gru_layer2_fc_kernel(const float* __restrict__ Wih,   // [96,32]
                          const float* __restrict__ Whh,   // [96,32]
                          const float* __restrict__ bih,   // [96]
                          const float* __restrict__ bhh,   // [96]
                          const float* __restrict__ Wfc2,  // [32,32]
                          const float* __restrict__ bfc2,  // [32]
                          const float* __restrict__ Wfc,   // [1,32]
                          const float* __restrict__ bfc,   // [1]
                          float* __restrict__ out)
{
    const int warp = (blockIdx.x * blockDim.x + threadIdx.x) >> 5;
    const int lane = threadIdx.x & 31;
    if (warp >= B_ROWS) return;

    float wir[HID], wiz[HID], win[HID];
    float whr[HID], whz[HID], whn[HID];
#pragma unroll
    for (int j = 0; j < HID; j++) {
        wir[j] = Wih[(lane)      * HID + j];
        wiz[j] = Wih[(32 + lane) * HID + j];
        win[j] = Wih[(64 + lane) * HID + j];
        whr[j] = Whh[(lane)      * HID + j];
        whz[j] = Whh[(32 + lane) * HID + j];
        whn[j] = Whh[(64 + lane) * HID + j];
    }
    const float br  = bih[lane]      + bhh[lane];
    const float bz  = bih[32 + lane] + bhh[32 + lane];
    const float bin = bih[64 + lane];
    const float bhn = bhh[64 + lane];

    const float* ip = g_h1 + (size_t)warp * SEQ * HID + lane;

    float h = 0.0f;
    float x_next = __ldg(ip);                 // prefetch step 0
#pragma unroll 1
    for (int s = 0; s < SEQ; s++) {
        const float x1 = x_next;              // this lane's h1[b][s][lane]
        if (s + 1 < SEQ) x_next = __ldg(ip + (size_t)(s + 1) * HID);

        float ar = br;
        float az = bz;
        float xn = bin;
        float hn = bhn;

#pragma unroll
        for (int j = 0; j < HID; j++) {
            const float aj = __shfl_sync(0xffffffffu, x1, j);  // h1 input
            const float hj = __shfl_sync(0xffffffffu, h,  j);  // recurrent h2
            ar = fmaf(wir[j], aj, ar);
            ar = fmaf(whr[j], hj, ar);
            az = fmaf(wiz[j], aj, az);
            az = fmaf(whz[j], hj, az);
            xn = fmaf(win[j], aj, xn);
            hn = fmaf(whn[j], hj, hn);
        }

        const float r = sigmoidf_fast(ar);
        const float z = sigmoidf_fast(az);
        const float n = tanhf_fast(fmaf(r, hn, xn));
        h = fmaf(z, h - n, n);
    }

    // FC2: o[lane] = W_fc2[lane,:] . h + b_fc2[lane]
    float o = __ldg(bfc2 + lane);
#pragma unroll
    for (int j = 0; j < HID; j++) {
        const float hj = __shfl_sync(0xffffffffu, h, j);
        o = fmaf(__ldg(Wfc2 + lane * HID + j), hj, o);
    }

    // FC: scalar = W_fc[0,:] . o + b_fc[0]
    float p = __ldg(Wfc + lane) * o;
#pragma unroll
    for (int off = 16; off > 0; off >>= 1)
        p += __shfl_xor_sync(0xffffffffu, p, off);

    if (lane == 0) out[warp] = p + __ldg(bfc);
}

// ---------------------------------------------------------------------------
// Launch
// ---------------------------------------------------------------------------
extern "C" void kernel_launch(void* const* d_in, const int* in_sizes, int n_in,
                              void* d_out, int out_size)
{
    const float* x     = (const float*)d_in[0];
    const float* Wih0  = (const float*)d_in[1];
    const float* Whh0  = (const float*)d_in[2];
    const float* bih0  = (const float*)d_in[3];
    const float* bhh0  = (const float*)d_in[4];
    const float* Wih1  = (const float*)d_in[5];
    const float* Whh1  = (const float*)d_in[6];
    const float* bih1  = (const float*)d_in[7];
    const float* bhh1  = (const float*)d_in[8];
    const float* Wfc2  = (const float*)d_in[9];
    const float* bfc2  = (const float*)d_in[10];
    const float* Wfc   = (const float*)d_in[11];
    const float* bfc   = (const float*)d_in[12];
    float* out = (float*)d_out;

    const int threads = 128;                       // 4 warps / CTA
    const int blocks  = B_ROWS / (threads / 32);   // 1024 CTAs

    gru_layer1_kernel<<<blocks, threads>>>(x, Wih0, Whh0, bih0, bhh0);
    gru_layer2_fc_kernel<<<blocks, threads>>>(Wih1, Whh1, bih1, bhh1,
                                              Wfc2, bfc2, Wfc, bfc, out);
}

// round 3
// speedup vs baseline: 1.4123x; 1.4123x over previous
#include <cuda_runtime.h>
#include <cuda_bf16.h>
#include <cstdint>

// ---------------------------------------------------------------------------
// 2-layer GRU (H=32, INPUT=4, B=4096, S=512) + FC(32->32) + FC(32->1)
//
// Warp per batch row, lane per hidden unit.
// - Gate dot products use packed fma.rn.f32x2 over (even j, odd j) pairs:
//   weight pairs are contiguous in the weight row, operand pairs are
//   contiguous in the broadcast h buffer -> no splat/pack instructions.
// - h broadcast via shared memory (STS.32 + 8 uniform LDS.128, double
//   buffered, one __syncwarp per step) instead of 32-64 shfls.
// - Gates via MUFU tanh.approx (sigmoid = 0.5*tanh(x/2)+0.5).
// ---------------------------------------------------------------------------

#define B_ROWS 4096
#define SEQ    512
#define HID    32

typedef unsigned long long ull;

// 4096*512*32 floats = 268 MB scratch for h1
__device__ float g_h1[(size_t)B_ROWS * SEQ * HID];

__device__ __forceinline__ ull ffma2(ull a, ull b, ull c) {
    ull d;
    asm("fma.rn.f32x2 %0, %1, %2, %3;" : "=l"(d) : "l"(a), "l"(b), "l"(c));
    return d;
}
__device__ __forceinline__ float2 unpack2(ull v) {
    float2 r;
    asm("mov.b64 {%0, %1}, %2;" : "=f"(r.x), "=f"(r.y) : "l"(v));
    return r;
}
__device__ __forceinline__ float hsum2(ull v) {
    float2 r = unpack2(v);
    return r.x + r.y;
}
__device__ __forceinline__ float tanh_ap(float x) {
    float y;
    asm("tanh.approx.f32 %0, %1;" : "=f"(y) : "f"(x));
    return y;
}
__device__ __forceinline__ float sig_ap(float x) {
    return fmaf(0.5f, tanh_ap(0.5f * x), 0.5f);
}

// ---------------------------------------------------------------------------
// Pass 1: GRU layer 1.  x:[B,S,4] -> h1:[B,S,32]
// ---------------------------------------------------------------------------
__global__ __launch_bounds__(128)
void gru_layer1_kernel(const float* __restrict__ x,
                       const float* __restrict__ Wih,   // [96,4]
                       const float* __restrict__ Whh,   // [96,32]
                       const float* __restrict__ bih,   // [96]
                       const float* __restrict__ bhh)   // [96]
{
    __shared__ __align__(16) float hbuf[4][2][HID];

    const int warp   = (blockIdx.x * blockDim.x + threadIdx.x) >> 5;
    const int wl     = threadIdx.x >> 5;
    const int lane   = threadIdx.x & 31;
    if (warp >= B_ROWS) return;

    // Recurrent weight rows for this lane's 3 gate outputs, packed by j-pair.
    ull whr[16], whz[16], whn[16];
    {
        const ull* pr = reinterpret_cast<const ull*>(Whh + (lane)      * HID);
        const ull* pz = reinterpret_cast<const ull*>(Whh + (32 + lane) * HID);
        const ull* pn = reinterpret_cast<const ull*>(Whh + (64 + lane) * HID);
#pragma unroll
        for (int k = 0; k < 16; k++) { whr[k] = pr[k]; whz[k] = pz[k]; whn[k] = pn[k]; }
    }
    const float4 wir = reinterpret_cast<const float4*>(Wih)[lane];
    const float4 wiz = reinterpret_cast<const float4*>(Wih)[32 + lane];
    const float4 win = reinterpret_cast<const float4*>(Wih)[64 + lane];

    const float br  = bih[lane]      + bhh[lane];
    const float bz  = bih[32 + lane] + bhh[32 + lane];
    const float bin = bih[64 + lane];
    const float bhn = bhh[64 + lane];

    const float4* xp = reinterpret_cast<const float4*>(x + (size_t)warp * SEQ * 4);
    float* op = g_h1 + (size_t)warp * SEQ * HID + lane;

    float h = 0.0f;
#pragma unroll 1
    for (int s = 0; s < SEQ; s++) {
        const float4 xv = __ldg(xp + s);

        // input contributions (scalar, only 4 wide)
        float ar = br, az = bz, xn = bin;
        ar = fmaf(wir.x, xv.x, ar); ar = fmaf(wir.y, xv.y, ar);
        ar = fmaf(wir.z, xv.z, ar); ar = fmaf(wir.w, xv.w, ar);
        az = fmaf(wiz.x, xv.x, az); az = fmaf(wiz.y, xv.y, az);
        az = fmaf(wiz.z, xv.z, az); az = fmaf(wiz.w, xv.w, az);
        xn = fmaf(win.x, xv.x, xn); xn = fmaf(win.y, xv.y, xn);
        xn = fmaf(win.z, xv.z, xn); xn = fmaf(win.w, xv.w, xn);

        // broadcast h through smem (double buffered)
        float* buf = hbuf[wl][s & 1];
        buf[lane] = h;
        __syncwarp();
        const ulonglong2* hp = reinterpret_cast<const ulonglong2*>(buf);

        ull accr = 0ull, accz = 0ull, accn = 0ull;
#pragma unroll
        for (int k = 0; k < 8; k++) {
            const ulonglong2 hv = hp[k];
            accr = ffma2(whr[2 * k],     hv.x, accr);
            accz = ffma2(whz[2 * k],     hv.x, accz);
            accn = ffma2(whn[2 * k],     hv.x, accn);
            accr = ffma2(whr[2 * k + 1], hv.y, accr);
            accz = ffma2(whz[2 * k + 1], hv.y, accz);
            accn = ffma2(whn[2 * k + 1], hv.y, accn);
        }
        ar += hsum2(accr);
        az += hsum2(accz);
        const float hn = bhn + hsum2(accn);

        const float r = sig_ap(ar);
        const float z = sig_ap(az);
        const float n = tanh_ap(fmaf(r, hn, xn));
        h = fmaf(z, h - n, n);

        op[(size_t)s * HID] = h;
    }
}

// ---------------------------------------------------------------------------
// Pass 2: GRU layer 2 + FC(32->32) + FC(32->1).  h1:[B,S,32] -> out:[B]
// ---------------------------------------------------------------------------
__global__ __launch_bounds__(128)
void gru_layer2_fc_kernel(const float* __restrict__ Wih,   // [96,32]
                          const float* __restrict__ Whh,   // [96,32]
                          const float* __restrict__ bih,   // [96]
                          const float* __restrict__ bhh,   // [96]
                          const float* __restrict__ Wfc2,  // [32,32]
                          const float* __restrict__ bfc2,  // [32]
                          const float* __restrict__ Wfc,   // [1,32]
                          const float* __restrict__ bfc,   // [1]
                          float* __restrict__ out)
{
    __shared__ __align__(16) float hbuf[4][2][HID];

    const int warp = (blockIdx.x * blockDim.x + threadIdx.x) >> 5;
    const int wl   = threadIdx.x >> 5;
    const int lane = threadIdx.x & 31;
    if (warp >= B_ROWS) return;

    ull wir[16], wiz[16], win[16], whr[16], whz[16], whn[16];
    {
        const ull* p0 = reinterpret_cast<const ull*>(Wih + (lane)      * HID);
        const ull* p1 = reinterpret_cast<const ull*>(Wih + (32 + lane) * HID);
        const ull* p2 = reinterpret_cast<const ull*>(Wih + (64 + lane) * HID);
        const ull* p3 = reinterpret_cast<const ull*>(Whh + (lane)      * HID);
        const ull* p4 = reinterpret_cast<const ull*>(Whh + (32 + lane) * HID);
        const ull* p5 = reinterpret_cast<const ull*>(Whh + (64 + lane) * HID);
#pragma unroll
        for (int k = 0; k < 16; k++) {
            wir[k] = p0[k]; wiz[k] = p1[k]; win[k] = p2[k];
            whr[k] = p3[k]; whz[k] = p4[k]; whn[k] = p5[k];
        }
    }
    const float br  = bih[lane]      + bhh[lane];
    const float bz  = bih[32 + lane] + bhh[32 + lane];
    const float bin = bih[64 + lane];
    const float bhn = bhh[64 + lane];

    const ulonglong2* xrow =
        reinterpret_cast<const ulonglong2*>(g_h1 + (size_t)warp * SEQ * HID);

    float h = 0.0f;
#pragma unroll 1
    for (int s = 0; s < SEQ; s++) {
        // broadcast recurrent h through smem (double buffered)
        float* buf = hbuf[wl][s & 1];
        buf[lane] = h;
        __syncwarp();
        const ulonglong2* hp = reinterpret_cast<const ulonglong2*>(buf);
        const ulonglong2* xp = xrow + (size_t)s * 8;  // h1 row, packed pairs

        ull ar2 = 0ull, az2 = 0ull, axn = 0ull, ahn = 0ull;
#pragma unroll
        for (int k = 0; k < 8; k++) {
            const ulonglong2 xv = xp[k];   // uniform LDG.128 (L1 broadcast)
            const ulonglong2 hv = hp[k];
            ar2 = ffma2(wir[2 * k],     xv.x, ar2);
            az2 = ffma2(wiz[2 * k],     xv.x, az2);
            axn = ffma2(win[2 * k],     xv.x, axn);
            ar2 = ffma2(whr[2 * k],     hv.x, ar2);
            az2 = ffma2(whz[2 * k],     hv.x, az2);
            ahn = ffma2(whn[2 * k],     hv.x, ahn);
            ar2 = ffma2(wir[2 * k + 1], xv.y, ar2);
            az2 = ffma2(wiz[2 * k + 1], xv.y, az2);
            axn = ffma2(win[2 * k + 1], xv.y, axn);
            ar2 = ffma2(whr[2 * k + 1], hv.y, ar2);
            az2 = ffma2(whz[2 * k + 1], hv.y, az2);
            ahn = ffma2(whn[2 * k + 1], hv.y, ahn);
        }
        const float ar = br  + hsum2(ar2);
        const float az = bz  + hsum2(az2);
        const float xn = bin + hsum2(axn);
        const float hn = bhn + hsum2(ahn);

        const float r = sig_ap(ar);
        const float z = sig_ap(az);
        const float n = tanh_ap(fmaf(r, hn, xn));
        h = fmaf(z, h - n, n);
    }

    // FC2: o[lane] = W_fc2[lane,:] . h + b_fc2[lane]  (reuse smem broadcast)
    {
        float* buf = hbuf[wl][0];
        buf[lane] = h;
        __syncwarp();
        const ulonglong2* hp = reinterpret_cast<const ulonglong2*>(buf);
        const ull* wf = reinterpret_cast<const ull*>(Wfc2 + lane * HID);
        ull acc = 0ull;
#pragma unroll
        for (int k = 0; k < 8; k++) {
            const ulonglong2 hv = hp[k];
            acc = ffma2(wf[2 * k],     hv.x, acc);
            acc = ffma2(wf[2 * k + 1], hv.y, acc);
        }
        const float o = __ldg(bfc2 + lane) + hsum2(acc);

        // FC: scalar = W_fc[0,:] . o + b_fc[0]
        float p = __ldg(Wfc + lane) * o;
#pragma unroll
        for (int off = 16; off > 0; off >>= 1)
            p += __shfl_xor_sync(0xffffffffu, p, off);
        if (lane == 0) out[warp] = p + __ldg(bfc);
    }
}

// ---------------------------------------------------------------------------
// Launch
// ---------------------------------------------------------------------------
extern "C" void kernel_launch(void* const* d_in, const int* in_sizes, int n_in,
                              void* d_out, int out_size)
{
    const float* x     = (const float*)d_in[0];
    const float* Wih0  = (const float*)d_in[1];
    const float* Whh0  = (const float*)d_in[2];
    const float* bih0  = (const float*)d_in[3];
    const float* bhh0  = (const float*)d_in[4];
    const float* Wih1  = (const float*)d_in[5];
    const float* Whh1  = (const float*)d_in[6];
    const float* bih1  = (const float*)d_in[7];
    const float* bhh1  = (const float*)d_in[8];
    const float* Wfc2  = (const float*)d_in[9];
    const float* bfc2  = (const float*)d_in[10];
    const float* Wfc   = (const float*)d_in[11];
    const float* bfc   = (const float*)d_in[12];
    float* out = (float*)d_out;

    const int threads = 128;
    const int blocks  = B_ROWS / (threads / 32);

    gru_layer1_kernel<<<blocks, threads>>>(x, Wih0, Whh0, bih0, bhh0);
    gru_layer2_fc_kernel<<<blocks, threads>>>(Wih1, Whh1, bih1, bhh1,
                                              Wfc2, bfc2, Wfc, bfc, out);
}